// round 16
// baseline (speedup 1.0000x reference)
#include <cuda_runtime.h>
#include <cuda_fp16.h>
#include <math.h>
#include <stdint.h>

#define TOK   50176      // B*H*W tokens
#define CDIM  512
#define HID   2048
#define NHEAD 16
#define NTOKW 49         // tokens per window
#define NWIN  1024       // B * 64

// ---------------- scratch (device globals; no allocation) ----------------
__device__ __half g_xw16  [(size_t)TOK * CDIM];
__device__ __half g_qkv16 [(size_t)TOK * 1536];
__device__ __half g_attn16[(size_t)TOK * CDIM];
__device__ __half g_proj16[(size_t)TOK * CDIM];
__device__ float  g_x1    [(size_t)TOK * CDIM];
__device__ __half g_x1h   [(size_t)TOK * CDIM];
__device__ __half g_hid16 [(size_t)TOK * HID];
__device__ __half g_h2h   [(size_t)TOK * CDIM];
__device__ float  g_table [169 * 16];
__device__ float  g_biasT [16 * 2401];
__device__ __half g_wt_qkv [1536 * 512];
__device__ __half g_wt_proj[512 * 512];
__device__ __half g_wt_fc1 [2048 * 512];
__device__ __half g_wt_fc2 [512 * 2048];

// ---------------- small helpers ----------------
__device__ __forceinline__ uint32_t smem_u32(const void* p) {
    uint32_t a;
    asm("{ .reg .u64 t; cvta.to.shared.u64 t, %1; cvt.u32.u64 %0, t; }" : "=r"(a) : "l"(p));
    return a;
}
__device__ __forceinline__ void ldsm4(uint32_t* r, uint32_t addr) {
    asm volatile("ldmatrix.sync.aligned.m8n8.x4.shared.b16 {%0,%1,%2,%3}, [%4];"
                 : "=r"(r[0]), "=r"(r[1]), "=r"(r[2]), "=r"(r[3]) : "r"(addr));
}
__device__ __forceinline__ void mma16816(float* c, const uint32_t* a, const uint32_t* b) {
    asm volatile("mma.sync.aligned.m16n8k16.row.col.f32.f16.f16.f32 "
                 "{%0,%1,%2,%3}, {%4,%5,%6,%7}, {%8,%9}, {%0,%1,%2,%3};"
                 : "+f"(c[0]), "+f"(c[1]), "+f"(c[2]), "+f"(c[3])
                 : "r"(a[0]), "r"(a[1]), "r"(a[2]), "r"(a[3]), "r"(b[0]), "r"(b[1]));
}
__device__ __forceinline__ void cp16(uint32_t dst, const void* src) {
    asm volatile("cp.async.cg.shared.global [%0], [%1], 16;"
                 :: "r"(dst), "l"(__cvta_generic_to_global(src)) : "memory");
}
#define CP_COMMIT() asm volatile("cp.async.commit_group;" ::: "memory")
#define CP_WAIT1()  asm volatile("cp.async.wait_group 1;" ::: "memory")

// fast GELU: Abramowitz-Stegun 7.1.26 erf (abs err 1.5e-7)
__device__ __forceinline__ float gelu_fast(float x) {
    float z = fabsf(x) * 0.70710678118654752f;
    float t = __frcp_rn(1.f + 0.3275911f * z);
    float p = t * (0.254829592f + t * (-0.284496736f + t * (1.421413741f +
              t * (-1.453152027f + t * 1.061405429f))));
    float er = 1.f - p * __expf(-z * z);
    er = copysignf(er, x);
    return 0.5f * x * (1.f + er);
}

// ---------------- index helpers ----------------
__device__ __forceinline__ int qkv_src_row(int t) {
    int b   = t / 3136;
    int r5  = t - b * 3136;
    int win = r5 / NTOKW;
    int n   = r5 - win * NTOKW;
    int wh = win >> 3, ww = win & 7;
    int rr = n / 7,    cc = n - (n / 7) * 7;
    int hs = wh * 7 + rr, ws = ww * 7 + cc;
    int h = hs + 3; if (h >= 56) h -= 56;
    int w = ws + 3; if (w >= 56) w -= 56;
    return (b * 56 + h) * 56 + w;
}

// ---------------- unified prep: 4 weight transposes + x gather -------------
__device__ __forceinline__ void do_transpose(const float* __restrict__ S,
                                             __half* __restrict__ D,
                                             int K, int N, int bx, int by, int tid) {
    __shared__ float t[32][33];
    int tx = tid & 31, ty = tid >> 5;
    int x = bx * 32 + tx;
    #pragma unroll
    for (int i = 0; i < 32; i += 8)
        t[ty + i][tx] = S[(size_t)(by * 32 + ty + i) * N + x];
    __syncthreads();
    int x2 = by * 32 + tx;
    #pragma unroll
    for (int i = 0; i < 32; i += 8)
        D[(size_t)(bx * 32 + ty + i) * K + x2] = __float2half_rn(t[tx][ty + i]);
}

__global__ __launch_bounds__(256)
void prep_kernel(const float* __restrict__ x,
                 const float* __restrict__ qkv_w, const float* __restrict__ proj_w,
                 const float* __restrict__ fc1_w, const float* __restrict__ fc2_w) {
    int b = blockIdx.x;
    int tid = threadIdx.x;
    if (b < 768) {
        do_transpose(qkv_w, g_wt_qkv, 512, 1536, b % 48, b / 48, tid);
    } else if (b < 1024) {
        int i = b - 768;
        do_transpose(proj_w, g_wt_proj, 512, 512, i % 16, i / 16, tid);
    } else if (b < 2048) {
        int i = b - 1024;
        do_transpose(fc1_w, g_wt_fc1, 512, 2048, i % 64, i / 64, tid);
    } else if (b < 3072) {
        int i = b - 2048;
        do_transpose(fc2_w, g_wt_fc2, 2048, 512, i % 16, i / 16, tid);
    } else {
        int token = (b - 3072) * 2 + (tid >> 7);
        int i4 = tid & 127;
        int src = qkv_src_row(token);
        float4 v = ((const float4*)x)[(size_t)src * 128 + i4];
        __half2* o = (__half2*)g_xw16 + (size_t)token * 256 + i4 * 2;
        o[0] = __floats2half2_rn(v.x, v.y);
        o[1] = __floats2half2_rn(v.z, v.w);
    }
}

// ---------------- CPB MLP: table[169][16] ----------------
__global__ void cpb_table_kernel(const float* __restrict__ rct,
                                 const float* __restrict__ w1,
                                 const float* __restrict__ b1,
                                 const float* __restrict__ w2) {
    int pos = blockIdx.x;
    float t0 = rct[pos * 2 + 0];
    float t1 = rct[pos * 2 + 1];
    __shared__ float hid[512];
    int j = threadIdx.x;
    float hv = t0 * w1[j] + t1 * w1[512 + j] + b1[j];
    hid[j] = fmaxf(hv, 0.f);
    __syncthreads();
    int warp = j >> 5, lane = j & 31;
    float s = 0.f;
    for (int jj = lane; jj < 512; jj += 32) s += hid[jj] * w2[jj * 16 + warp];
    #pragma unroll
    for (int o = 16; o > 0; o >>= 1) s += __shfl_down_sync(0xffffffffu, s, o);
    if (lane == 0) g_table[pos * 16 + warp] = s;
}

__global__ void bias_expand_kernel(const int* __restrict__ rpi) {
    int i = blockIdx.x * blockDim.x + threadIdx.x;
    if (i >= 16 * 2401) return;
    int h = i / 2401, nm = i - h * 2401;
    float v = g_table[rpi[nm] * 16 + h];
    g_biasT[i] = 16.f / (1.f + __expf(-v));
}

// ---------------- fp16 tensor-core GEMM (round-12 config) -----------------
#define MODE_BIAS      0
#define MODE_QKV       1
#define MODE_GELU_H    2

#define ROWB   128
#define STAGE  (256 * ROWB)        // 32768 B
#define BOFF_B (128 * ROWB)
#define HG_SMEM (3 * STAGE)        // 98304 B

template <int MODE, int TXFAST>
__global__ __launch_bounds__(256, 2)
void hgemm_kernel(const __half* __restrict__ A, const __half* __restrict__ Wt,
                  __half* __restrict__ C, int M, int N, int K,
                  const float* __restrict__ bias, const float* __restrict__ bias2) {
    extern __shared__ char smc[];
    const uint32_t sb = smem_u32(smc);
    const int tid  = threadIdx.x;
    const int lane = tid & 31;
    const int wid  = tid >> 5;

    const int ldRow  = tid >> 1;
    const int ldHalf = tid & 1;
    uint32_t dA[4], dB[4];
    #pragma unroll
    for (int j = 0; j < 4; j++) {
        int phys = (ldHalf * 4 + j) ^ (ldRow & 7);
        dA[j] = sb + (uint32_t)ldRow * ROWB + phys * 16;
        dB[j] = dA[j] + BOFF_B;
    }

    const int wm = (wid >> 2) * 64;
    const int wn = (wid & 3) * 32;
    const int aRow = wm + (lane & 15);
    const int aLC  = (lane >> 4);
    const int bRow = wn + (lane & 7) + ((lane >> 4) & 1) * 8;
    const int bLC  = ((lane >> 3) & 1);
    const uint32_t aRowAddr = sb + (uint32_t)aRow * ROWB;
    const uint32_t bRowAddr = sb + BOFF_B + (uint32_t)bRow * ROWB;
    const int aSw = (aRow & 7), bSw = (bRow & 7), bSw2 = ((bRow + 16) & 7);

    const int KT = K / 64;
    const int tilesY = M >> 7, tilesX = N >> 7;
    const int nTiles = tilesX * tilesY;

    for (int tile = blockIdx.x; tile < nTiles; tile += gridDim.x) {
        int tx, ty;
        if (TXFAST) {
            ty = tile / tilesX;
            tx = tile - ty * tilesX;
        } else {
            tx = tile / tilesY;
            ty = tile - tx * tilesY;
        }
        const int rowBase = ty << 7;
        const int colBase = tx << 7;
        const __half* gA = A  + (size_t)(rowBase + ldRow) * K + ldHalf * 32;
        const __half* gB = Wt + (size_t)(colBase + ldRow) * K + ldHalf * 32;

        float acc[4][4][4];
        #pragma unroll
        for (int m = 0; m < 4; m++)
            #pragma unroll
            for (int f = 0; f < 4; f++)
                #pragma unroll
                for (int q = 0; q < 4; q++) acc[m][f][q] = 0.f;

        __syncthreads();

        #pragma unroll
        for (int s = 0; s < 2; s++) {
            #pragma unroll
            for (int j = 0; j < 4; j++) {
                cp16(dA[j] + s * STAGE, gA + s * 64 + j * 8);
                cp16(dB[j] + s * STAGE, gB + s * 64 + j * 8);
            }
            CP_COMMIT();
        }

        for (int kt = 0; kt < KT; kt++) {
            CP_WAIT1();
            __syncthreads();

            if (kt + 2 < KT) {
                const uint32_t so = (uint32_t)((kt + 2) % 3) * STAGE;
                #pragma unroll
                for (int j = 0; j < 4; j++) {
                    cp16(dA[j] + so, gA + (kt + 2) * 64 + j * 8);
                    cp16(dB[j] + so, gB + (kt + 2) * 64 + j * 8);
                }
            }
            CP_COMMIT();

            const uint32_t stOff = (uint32_t)(kt % 3) * STAGE;
            #pragma unroll
            for (int ks = 0; ks < 4; ks++) {
                uint32_t a[4][4], bt0[4], bt1[4];
                #pragma unroll
                for (int m = 0; m < 4; m++) {
                    int phys = (aLC + 2 * ks) ^ aSw;
                    ldsm4(a[m], stOff + aRowAddr + m * 16 * ROWB + phys * 16);
                }
                {
                    int phys0 = (bLC + 2 * ks) ^ bSw;
                    int phys1 = (bLC + 2 * ks) ^ bSw2;
                    ldsm4(bt0, stOff + bRowAddr + phys0 * 16);
                    ldsm4(bt1, stOff + bRowAddr + 16 * ROWB + phys1 * 16);
                }
                uint32_t bf[4][2] = {{bt0[0], bt0[1]}, {bt0[2], bt0[3]},
                                     {bt1[0], bt1[1]}, {bt1[2], bt1[3]}};
                #pragma unroll
                for (int m = 0; m < 4; m++)
                    #pragma unroll
                    for (int f = 0; f < 4; f++)
                        mma16816(acc[m][f], a[m], bf[f]);
            }
        }

        #pragma unroll
        for (int m = 0; m < 4; m++) {
            int r0 = rowBase + wm + m * 16 + (lane >> 2);
            #pragma unroll
            for (int f = 0; f < 4; f++) {
                int c = colBase + wn + f * 8 + (lane & 3) * 2;
                float v0 = acc[m][f][0], v1 = acc[m][f][1];
                float v2 = acc[m][f][2], v3 = acc[m][f][3];
                if (MODE == MODE_QKV) {
                    float b0 = (c < 512) ? bias[c] : ((c < 1024) ? 0.f : bias2[c - 1024]);
                    float b1 = (c + 1 < 512) ? bias[c + 1] : ((c + 1 < 1024) ? 0.f : bias2[c + 1 - 1024]);
                    v0 += b0; v1 += b1; v2 += b0; v3 += b1;
                } else {
                    v0 += bias[c]; v1 += bias[c + 1]; v2 += bias[c]; v3 += bias[c + 1];
                }
                if (MODE == MODE_GELU_H) {
                    v0 = gelu_fast(v0);
                    v1 = gelu_fast(v1);
                    v2 = gelu_fast(v2);
                    v3 = gelu_fast(v3);
                }
                *(__half2*)(C + (size_t)r0 * N + c)       = __floats2half2_rn(v0, v1);
                *(__half2*)(C + (size_t)(r0 + 8) * N + c) = __floats2half2_rn(v2, v3);
            }
        }
    }
}

// ---------------- attention: vectorized register-blocked ------------------
#define KTS 50   // kt/S row stride (padded, even; col 49 zeroed)

__global__ __launch_bounds__(256)
void attn_kernel(const float* __restrict__ mask,
                 const float* __restrict__ logit_scale) {
    int blk  = blockIdx.x;
    int win  = blk >> 4;
    int head = blk & 15;
    __shared__ float qs[NTOKW * 32];       // [n][d], pre-scaled by rqn*scale
    __shared__ float kt[32 * KTS];         // [d][m], pre-scaled by rkn, padded
    __shared__ float vs[NTOKW * 32];       // [m][d]
    __shared__ float S[NTOKW * KTS];       // padded rows
    __shared__ float rqn[NTOKW], rkn[NTOKW];
    int tid = threadIdx.x;
    int lane = tid & 31, w = tid >> 5;

    const __half* base = g_qkv16 + (size_t)win * NTOKW * 1536 + head * 32;
    if (tid < NTOKW * 4) {
        int n = tid >> 2, c8 = tid & 3;
        const __half* src = base + (size_t)n * 1536 + c8 * 8;
        uint4 uq = *(const uint4*)(src);
        uint4 uk = *(const uint4*)(src + 512);
        uint4 uv = *(const uint4*)(src + 1024);
        const __half2* hq = (const __half2*)&uq;
        const __half2* hk = (const __half2*)&uk;
        const __half2* hv = (const __half2*)&uv;
        #pragma unroll
        for (int e = 0; e < 4; e++) {
            float2 fq = __half22float2(hq[e]);
            float2 fk = __half22float2(hk[e]);
            float2 fv = __half22float2(hv[e]);
            int d = c8 * 8 + 2 * e;
            qs[n * 32 + d] = fq.x;  qs[n * 32 + d + 1] = fq.y;
            kt[d * KTS + n] = fk.x;  kt[(d + 1) * KTS + n] = fk.y;
            vs[n * 32 + d] = fv.x;  vs[n * 32 + d + 1] = fv.y;
        }
    }
    if (tid < 32) kt[tid * KTS + 49] = 0.f;   // zero pad column
    __syncthreads();

    float scale = __expf(fminf(logit_scale[head], 4.6051701859880914f));
    if (tid < 2 * NTOKW) {
        int n = tid % NTOKW;
        float s = 0.f;
        if (tid < NTOKW) {
            const float* p = qs + n * 32;
            #pragma unroll
            for (int d = 0; d < 32; d++) { float v = p[d]; s += v * v; }
            rqn[n] = rsqrtf(s) * scale;
        } else {
            #pragma unroll
            for (int d = 0; d < 32; d++) { float v = kt[d * KTS + n]; s += v * v; }
            rkn[n] = rsqrtf(s);
        }
    }
    __syncthreads();

    // pre-scale q rows (by rqn*scale) and k columns (by rkn) in smem
    // (d = i / NTOKW in [0,32), m = i % NTOKW in [0,49) -- full coverage, once each)
    for (int i = tid; i < NTOKW * 32; i += 256) {
        qs[i] *= rqn[i >> 5];
        int d = i / NTOKW, m = i - d * NTOKW;
        kt[d * KTS + m] *= rkn[m];
    }
    __syncthreads();

    // S loop: thread (n, g) handles m-pairs pm = g, g+5, ..., g+20 (m = 2*pm)
    const float* bh = g_biasT + head * 2401;
    const float* mw = mask + (size_t)(win & 63) * 2401;
    if (tid < 245) {
        int n = tid / 5, g = tid % 5;
        float qp[32];
        #pragma unroll
        for (int d = 0; d < 32; d++) qp[d] = qs[n * 32 + d];
        #pragma unroll
        for (int j = 0; j < 5; j++) {
            int m = 2 * (g + 5 * j);
            float s0 = 0.f, s1 = 0.f;
            #pragma unroll
            for (int d = 0; d < 32; d++) {
                float2 kk = *(const float2*)(kt + d * KTS + m);
                s0 += qp[d] * kk.x;
                s1 += qp[d] * kk.y;
            }
            int p = n * NTOKW + m;
            S[n * KTS + m] = s0 + bh[p] + mw[p];
            if (m + 1 < NTOKW)
                S[n * KTS + m + 1] = s1 + bh[p + 1] + mw[p + 1];
        }
    }
    __syncthreads();

    // softmax (warp-parallel over rows)
    for (int r = w; r < NTOKW; r += 8) {
        float* row = S + r * KTS;
        float v0 = row[lane];
        float v1 = (lane < 17) ? row[32 + lane] : -1e30f;
        float mx = fmaxf(v0, v1);
        #pragma unroll
        for (int o = 16; o > 0; o >>= 1) mx = fmaxf(mx, __shfl_xor_sync(0xffffffffu, mx, o));
        float e0 = __expf(v0 - mx);
        float e1 = (lane < 17) ? __expf(v1 - mx) : 0.f;
        float s = e0 + e1;
        #pragma unroll
        for (int o = 16; o > 0; o >>= 1) s += __shfl_xor_sync(0xffffffffu, s, o);
        float inv = 1.f / s;
        row[lane] = e0 * inv;
        if (lane < 17) row[32 + lane] = e1 * inv;
    }
    __syncthreads();

    // AV: thread (n, dg) computes 8 d's; vs rows loaded as 2x float4
    if (tid < 196) {
        int n = tid >> 2, dg = (tid & 3) * 8;
        const float* Pr = S + n * KTS;
        float acc[8];
        #pragma unroll
        for (int j = 0; j < 8; j++) acc[j] = 0.f;
        for (int m = 0; m < NTOKW; m++) {
            float p = Pr[m];
            float4 v0 = *(const float4*)(vs + m * 32 + dg);
            float4 v1 = *(const float4*)(vs + m * 32 + dg + 4);
            acc[0] += p * v0.x; acc[1] += p * v0.y;
            acc[2] += p * v0.z; acc[3] += p * v0.w;
            acc[4] += p * v1.x; acc[5] += p * v1.y;
            acc[6] += p * v1.z; acc[7] += p * v1.w;
        }
        __half2* o = (__half2*)(g_attn16 + (size_t)(win * NTOKW + n) * CDIM + head * 32 + dg);
        #pragma unroll
        for (int j = 0; j < 4; j++)
            o[j] = __floats2half2_rn(acc[2 * j], acc[2 * j + 1]);
    }
}

// ---------------- LN kernels: warp per row, fp16 inputs ----------------
__global__ __launch_bounds__(256)
void post_attn_kernel(const float* __restrict__ x,
                      const float* __restrict__ g1, const float* __restrict__ b1) {
    int lane = threadIdx.x & 31;
    int p = blockIdx.x * 8 + (threadIdx.x >> 5);
    int b = p / 3136, rem = p - b * 3136;
    int h = rem / 56, w = rem - (rem / 56) * 56;
    int hs = h - 3; if (hs < 0) hs += 56;
    int ws = w - 3; if (ws < 0) ws += 56;
    int t = (b * 64 + (hs / 7) * 8 + (ws / 7)) * NTOKW + (hs % 7) * 7 + (ws % 7);

    const __half2* row = (const __half2*)(g_proj16 + (size_t)t * CDIM);
    float2 v[8];
    float s = 0.f, ss = 0.f;
    #pragma unroll
    for (int k = 0; k < 8; k++) {
        v[k] = __half22float2(row[lane + k * 32]);
        s  += v[k].x + v[k].y;
        ss += v[k].x * v[k].x + v[k].y * v[k].y;
    }
    #pragma unroll
    for (int o = 16; o > 0; o >>= 1) {
        s  += __shfl_xor_sync(0xffffffffu, s,  o);
        ss += __shfl_xor_sync(0xffffffffu, ss, o);
    }
    float mu = s * (1.f / CDIM);
    float rstd = rsqrtf(ss * (1.f / CDIM) - mu * mu + 1e-5f);
    const float2* xr = (const float2*)(x + (size_t)p * CDIM);
    float2* o1 = (float2*)(g_x1 + (size_t)p * CDIM);
    __half2* oh = (__half2*)(g_x1h + (size_t)p * CDIM);
    #pragma unroll
    for (int k = 0; k < 8; k++) {
        int c = (lane + k * 32) * 2;
        float2 xv = xr[lane + k * 32];
        float ox = xv.x + (v[k].x - mu) * rstd * g1[c + 0] + b1[c + 0];
        float oy = xv.y + (v[k].y - mu) * rstd * g1[c + 1] + b1[c + 1];
        o1[lane + k * 32] = make_float2(ox, oy);
        oh[lane + k * 32] = __floats2half2_rn(ox, oy);
    }
}

__global__ __launch_bounds__(256)
void final_kernel(const float* __restrict__ g2, const float* __restrict__ b2,
                  float* __restrict__ out) {
    int lane = threadIdx.x & 31;
    int p = blockIdx.x * 8 + (threadIdx.x >> 5);
    const __half2* row = (const __half2*)(g_h2h + (size_t)p * CDIM);
    float2 v[8];
    float s = 0.f, ss = 0.f;
    #pragma unroll
    for (int k = 0; k < 8; k++) {
        v[k] = __half22float2(row[lane + k * 32]);
        s  += v[k].x + v[k].y;
        ss += v[k].x * v[k].x + v[k].y * v[k].y;
    }
    #pragma unroll
    for (int o = 16; o > 0; o >>= 1) {
        s  += __shfl_xor_sync(0xffffffffu, s,  o);
        ss += __shfl_xor_sync(0xffffffffu, ss, o);
    }
    float mu = s * (1.f / CDIM);
    float rstd = rsqrtf(ss * (1.f / CDIM) - mu * mu + 1e-5f);
    const float2* xr = (const float2*)(g_x1 + (size_t)p * CDIM);
    float2* o1 = (float2*)(out + (size_t)p * CDIM);
    #pragma unroll
    for (int k = 0; k < 8; k++) {
        int c = (lane + k * 32) * 2;
        float2 xv = xr[lane + k * 32];
        float ox = xv.x + (v[k].x - mu) * rstd * g2[c + 0] + b2[c + 0];
        float oy = xv.y + (v[k].y - mu) * rstd * g2[c + 1] + b2[c + 1];
        o1[lane + k * 32] = make_float2(ox, oy);
    }
}

// ---------------- launch ----------------
extern "C" void kernel_launch(void* const* d_in, const int* in_sizes, int n_in,
                              void* d_out, int out_size) {
    const float* x        = (const float*)d_in[0];
    const float* qkv_w    = (const float*)d_in[1];
    const float* q_bias   = (const float*)d_in[2];
    const float* v_bias   = (const float*)d_in[3];
    const float* proj_w   = (const float*)d_in[4];
    const float* proj_b   = (const float*)d_in[5];
    const float* lscale   = (const float*)d_in[6];
    const float* cpb_w1   = (const float*)d_in[7];
    const float* cpb_b1   = (const float*)d_in[8];
    const float* cpb_w2   = (const float*)d_in[9];
    const float* rct      = (const float*)d_in[10];
    const float* gamma1   = (const float*)d_in[11];
    const float* beta1    = (const float*)d_in[12];
    const float* gamma2   = (const float*)d_in[13];
    const float* beta2    = (const float*)d_in[14];
    const float* fc1_w    = (const float*)d_in[15];
    const float* fc1_b    = (const float*)d_in[16];
    const float* fc2_w    = (const float*)d_in[17];
    const float* fc2_b    = (const float*)d_in[18];
    const int*   rpi      = (const int*)d_in[19];
    const float* amask    = (const float*)d_in[20];
    float* out = (float*)d_out;

    __half *p_xw16, *p_qkv16, *p_attn16, *p_proj16, *p_x1h, *p_hid16, *p_h2h;
    __half *wt_qkv, *wt_proj, *wt_fc1, *wt_fc2;
    cudaGetSymbolAddress((void**)&p_xw16,   g_xw16);
    cudaGetSymbolAddress((void**)&p_qkv16,  g_qkv16);
    cudaGetSymbolAddress((void**)&p_attn16, g_attn16);
    cudaGetSymbolAddress((void**)&p_proj16, g_proj16);
    cudaGetSymbolAddress((void**)&p_x1h,    g_x1h);
    cudaGetSymbolAddress((void**)&p_hid16,  g_hid16);
    cudaGetSymbolAddress((void**)&p_h2h,    g_h2h);
    cudaGetSymbolAddress((void**)&wt_qkv,   g_wt_qkv);
    cudaGetSymbolAddress((void**)&wt_proj,  g_wt_proj);
    cudaGetSymbolAddress((void**)&wt_fc1,   g_wt_fc1);
    cudaGetSymbolAddress((void**)&wt_fc2,   g_wt_fc2);

    cudaFuncSetAttribute((const void*)hgemm_kernel<MODE_QKV, 0>,
                         cudaFuncAttributeMaxDynamicSharedMemorySize, HG_SMEM);
    cudaFuncSetAttribute((const void*)hgemm_kernel<MODE_BIAS, 0>,
                         cudaFuncAttributeMaxDynamicSharedMemorySize, HG_SMEM);
    cudaFuncSetAttribute((const void*)hgemm_kernel<MODE_GELU_H, 0>,
                         cudaFuncAttributeMaxDynamicSharedMemorySize, HG_SMEM);
    cudaFuncSetAttribute((const void*)hgemm_kernel<MODE_BIAS, 1>,
                         cudaFuncAttributeMaxDynamicSharedMemorySize, HG_SMEM);

    int dev = 0, nsm = 148;
    cudaGetDevice(&dev);
    cudaDeviceGetAttribute(&nsm, cudaDevAttrMultiProcessorCount, dev);
    const int PGRID = nsm * 2;   // persistent grid, 2 CTAs/SM

    // 0. fused prep
    prep_kernel<<<3072 + TOK / 2, 256>>>(x, qkv_w, proj_w, fc1_w, fc2_w);

    // 1. continuous position bias
    cpb_table_kernel<<<169, 512>>>(rct, cpb_w1, cpb_b1, cpb_w2);
    bias_expand_kernel<<<(16 * 2401 + 255) / 256, 256>>>(rpi);

    // 2. QKV GEMM
    hgemm_kernel<MODE_QKV, 0><<<PGRID, 256, HG_SMEM>>>(
        p_xw16, wt_qkv, p_qkv16, TOK, 1536, 512, q_bias, v_bias);

    // 3. windowed cosine attention
    attn_kernel<<<NWIN * NHEAD, 256>>>(amask, lscale);

    // 4. output projection
    hgemm_kernel<MODE_BIAS, 0><<<PGRID, 256, HG_SMEM>>>(
        p_attn16, wt_proj, p_proj16, TOK, CDIM, CDIM, proj_b, nullptr);

    // 5. window reverse + un-roll + LN + residual
    post_attn_kernel<<<TOK / 8, 256>>>(x, gamma1, beta1);

    // 6. MLP (fc2 tx-fastest: A exceeds L2)
    hgemm_kernel<MODE_GELU_H, 0><<<PGRID, 256, HG_SMEM>>>(
        p_x1h, wt_fc1, p_hid16, TOK, HID, 512, fc1_b, nullptr);
    hgemm_kernel<MODE_BIAS, 1><<<PGRID, 256, HG_SMEM>>>(
        p_hid16, wt_fc2, p_h2h, TOK, CDIM, HID, fc2_b, nullptr);

    // 7. final LN + residual
    final_kernel<<<TOK / 8, 256>>>(gamma2, beta2, out);
}

// round 17
// speedup vs baseline: 1.0102x; 1.0102x over previous
#include <cuda_runtime.h>
#include <cuda_fp16.h>
#include <math.h>
#include <stdint.h>

#define TOK   50176      // B*H*W tokens
#define CDIM  512
#define HID   2048
#define NHEAD 16
#define NTOKW 49         // tokens per window
#define NWIN  1024       // B * 64

// ---------------- scratch (device globals; no allocation) ----------------
__device__ __half g_xw16  [(size_t)TOK * CDIM];
__device__ __half g_qkv16 [(size_t)TOK * 1536];
__device__ __half g_attn16[(size_t)TOK * CDIM];
__device__ __half g_proj16[(size_t)TOK * CDIM];
__device__ float  g_x1    [(size_t)TOK * CDIM];
__device__ __half g_x1h   [(size_t)TOK * CDIM];
__device__ __half g_hid16 [(size_t)TOK * HID];
__device__ __half g_h2h   [(size_t)TOK * CDIM];
__device__ float  g_table [169 * 16];
__device__ float  g_bm    [64 * 16 * 2401];   // combined bias+mask table
__device__ __half g_wt_qkv [1536 * 512];
__device__ __half g_wt_proj[512 * 512];
__device__ __half g_wt_fc1 [2048 * 512];
__device__ __half g_wt_fc2 [512 * 2048];

// ---------------- small helpers ----------------
__device__ __forceinline__ uint32_t smem_u32(const void* p) {
    uint32_t a;
    asm("{ .reg .u64 t; cvta.to.shared.u64 t, %1; cvt.u32.u64 %0, t; }" : "=r"(a) : "l"(p));
    return a;
}
__device__ __forceinline__ void ldsm4(uint32_t* r, uint32_t addr) {
    asm volatile("ldmatrix.sync.aligned.m8n8.x4.shared.b16 {%0,%1,%2,%3}, [%4];"
                 : "=r"(r[0]), "=r"(r[1]), "=r"(r[2]), "=r"(r[3]) : "r"(addr));
}
__device__ __forceinline__ void mma16816(float* c, const uint32_t* a, const uint32_t* b) {
    asm volatile("mma.sync.aligned.m16n8k16.row.col.f32.f16.f16.f32 "
                 "{%0,%1,%2,%3}, {%4,%5,%6,%7}, {%8,%9}, {%0,%1,%2,%3};"
                 : "+f"(c[0]), "+f"(c[1]), "+f"(c[2]), "+f"(c[3])
                 : "r"(a[0]), "r"(a[1]), "r"(a[2]), "r"(a[3]), "r"(b[0]), "r"(b[1]));
}
__device__ __forceinline__ void cp16(uint32_t dst, const void* src) {
    asm volatile("cp.async.cg.shared.global [%0], [%1], 16;"
                 :: "r"(dst), "l"(__cvta_generic_to_global(src)) : "memory");
}
#define CP_COMMIT() asm volatile("cp.async.commit_group;" ::: "memory")
#define CP_WAIT1()  asm volatile("cp.async.wait_group 1;" ::: "memory")

// fast GELU: Abramowitz-Stegun 7.1.26 erf (abs err 1.5e-7)
__device__ __forceinline__ float gelu_fast(float x) {
    float z = fabsf(x) * 0.70710678118654752f;
    float t = __frcp_rn(1.f + 0.3275911f * z);
    float p = t * (0.254829592f + t * (-0.284496736f + t * (1.421413741f +
              t * (-1.453152027f + t * 1.061405429f))));
    float er = 1.f - p * __expf(-z * z);
    er = copysignf(er, x);
    return 0.5f * x * (1.f + er);
}

// ---------------- index helpers ----------------
__device__ __forceinline__ int qkv_src_row(int t) {
    int b   = t / 3136;
    int r5  = t - b * 3136;
    int win = r5 / NTOKW;
    int n   = r5 - win * NTOKW;
    int wh = win >> 3, ww = win & 7;
    int rr = n / 7,    cc = n - (n / 7) * 7;
    int hs = wh * 7 + rr, ws = ww * 7 + cc;
    int h = hs + 3; if (h >= 56) h -= 56;
    int w = ws + 3; if (w >= 56) w -= 56;
    return (b * 56 + h) * 56 + w;
}

// ---------------- unified prep: 4 weight transposes + x gather -------------
__device__ __forceinline__ void do_transpose(const float* __restrict__ S,
                                             __half* __restrict__ D,
                                             int K, int N, int bx, int by, int tid) {
    __shared__ float t[32][33];
    int tx = tid & 31, ty = tid >> 5;
    int x = bx * 32 + tx;
    #pragma unroll
    for (int i = 0; i < 32; i += 8)
        t[ty + i][tx] = S[(size_t)(by * 32 + ty + i) * N + x];
    __syncthreads();
    int x2 = by * 32 + tx;
    #pragma unroll
    for (int i = 0; i < 32; i += 8)
        D[(size_t)(bx * 32 + ty + i) * K + x2] = __float2half_rn(t[tx][ty + i]);
}

__global__ __launch_bounds__(256)
void prep_kernel(const float* __restrict__ x,
                 const float* __restrict__ qkv_w, const float* __restrict__ proj_w,
                 const float* __restrict__ fc1_w, const float* __restrict__ fc2_w) {
    int b = blockIdx.x;
    int tid = threadIdx.x;
    if (b < 768) {
        do_transpose(qkv_w, g_wt_qkv, 512, 1536, b % 48, b / 48, tid);
    } else if (b < 1024) {
        int i = b - 768;
        do_transpose(proj_w, g_wt_proj, 512, 512, i % 16, i / 16, tid);
    } else if (b < 2048) {
        int i = b - 1024;
        do_transpose(fc1_w, g_wt_fc1, 512, 2048, i % 64, i / 64, tid);
    } else if (b < 3072) {
        int i = b - 2048;
        do_transpose(fc2_w, g_wt_fc2, 2048, 512, i % 16, i / 16, tid);
    } else {
        int token = (b - 3072) * 2 + (tid >> 7);
        int i4 = tid & 127;
        int src = qkv_src_row(token);
        float4 v = ((const float4*)x)[(size_t)src * 128 + i4];
        __half2* o = (__half2*)g_xw16 + (size_t)token * 256 + i4 * 2;
        o[0] = __floats2half2_rn(v.x, v.y);
        o[1] = __floats2half2_rn(v.z, v.w);
    }
}

// ---------------- CPB MLP: table[169][16] ----------------
__global__ void cpb_table_kernel(const float* __restrict__ rct,
                                 const float* __restrict__ w1,
                                 const float* __restrict__ b1,
                                 const float* __restrict__ w2) {
    int pos = blockIdx.x;
    float t0 = rct[pos * 2 + 0];
    float t1 = rct[pos * 2 + 1];
    __shared__ float hid[512];
    int j = threadIdx.x;
    float hv = t0 * w1[j] + t1 * w1[512 + j] + b1[j];
    hid[j] = fmaxf(hv, 0.f);
    __syncthreads();
    int warp = j >> 5, lane = j & 31;
    float s = 0.f;
    for (int jj = lane; jj < 512; jj += 32) s += hid[jj] * w2[jj * 16 + warp];
    #pragma unroll
    for (int o = 16; o > 0; o >>= 1) s += __shfl_down_sync(0xffffffffu, s, o);
    if (lane == 0) g_table[pos * 16 + warp] = s;
}

// combined bias+mask table: g_bm[w64][head][p] = 16*sigmoid(table[rpi[p]][head]) + mask[w64][p]
__global__ void bm_kernel(const int* __restrict__ rpi, const float* __restrict__ mask) {
    int i = blockIdx.x * blockDim.x + threadIdx.x;   // 64*16*2401
    if (i >= 64 * 16 * 2401) return;
    int w64 = i / (16 * 2401);
    int r   = i - w64 * 16 * 2401;
    int h   = r / 2401, nm = r - h * 2401;
    float v = g_table[rpi[nm] * 16 + h];
    g_bm[i] = 16.f / (1.f + __expf(-v)) + mask[w64 * 2401 + nm];
}

// ---------------- fp16 tensor-core GEMM (round-12 config) -----------------
#define MODE_BIAS      0
#define MODE_QKV       1
#define MODE_GELU_H    2

#define ROWB   128
#define STAGE  (256 * ROWB)        // 32768 B
#define BOFF_B (128 * ROWB)
#define HG_SMEM (3 * STAGE)        // 98304 B

template <int MODE, int TXFAST>
__global__ __launch_bounds__(256, 2)
void hgemm_kernel(const __half* __restrict__ A, const __half* __restrict__ Wt,
                  __half* __restrict__ C, int M, int N, int K,
                  const float* __restrict__ bias, const float* __restrict__ bias2) {
    extern __shared__ char smc[];
    const uint32_t sb = smem_u32(smc);
    const int tid  = threadIdx.x;
    const int lane = tid & 31;
    const int wid  = tid >> 5;

    const int ldRow  = tid >> 1;
    const int ldHalf = tid & 1;
    uint32_t dA[4], dB[4];
    #pragma unroll
    for (int j = 0; j < 4; j++) {
        int phys = (ldHalf * 4 + j) ^ (ldRow & 7);
        dA[j] = sb + (uint32_t)ldRow * ROWB + phys * 16;
        dB[j] = dA[j] + BOFF_B;
    }

    const int wm = (wid >> 2) * 64;
    const int wn = (wid & 3) * 32;
    const int aRow = wm + (lane & 15);
    const int aLC  = (lane >> 4);
    const int bRow = wn + (lane & 7) + ((lane >> 4) & 1) * 8;
    const int bLC  = ((lane >> 3) & 1);
    const uint32_t aRowAddr = sb + (uint32_t)aRow * ROWB;
    const uint32_t bRowAddr = sb + BOFF_B + (uint32_t)bRow * ROWB;
    const int aSw = (aRow & 7), bSw = (bRow & 7), bSw2 = ((bRow + 16) & 7);

    const int KT = K / 64;
    const int tilesY = M >> 7, tilesX = N >> 7;
    const int nTiles = tilesX * tilesY;

    for (int tile = blockIdx.x; tile < nTiles; tile += gridDim.x) {
        int tx, ty;
        if (TXFAST) {
            ty = tile / tilesX;
            tx = tile - ty * tilesX;
        } else {
            tx = tile / tilesY;
            ty = tile - tx * tilesY;
        }
        const int rowBase = ty << 7;
        const int colBase = tx << 7;
        const __half* gA = A  + (size_t)(rowBase + ldRow) * K + ldHalf * 32;
        const __half* gB = Wt + (size_t)(colBase + ldRow) * K + ldHalf * 32;

        float acc[4][4][4];
        #pragma unroll
        for (int m = 0; m < 4; m++)
            #pragma unroll
            for (int f = 0; f < 4; f++)
                #pragma unroll
                for (int q = 0; q < 4; q++) acc[m][f][q] = 0.f;

        __syncthreads();

        #pragma unroll
        for (int s = 0; s < 2; s++) {
            #pragma unroll
            for (int j = 0; j < 4; j++) {
                cp16(dA[j] + s * STAGE, gA + s * 64 + j * 8);
                cp16(dB[j] + s * STAGE, gB + s * 64 + j * 8);
            }
            CP_COMMIT();
        }

        for (int kt = 0; kt < KT; kt++) {
            CP_WAIT1();
            __syncthreads();

            if (kt + 2 < KT) {
                const uint32_t so = (uint32_t)((kt + 2) % 3) * STAGE;
                #pragma unroll
                for (int j = 0; j < 4; j++) {
                    cp16(dA[j] + so, gA + (kt + 2) * 64 + j * 8);
                    cp16(dB[j] + so, gB + (kt + 2) * 64 + j * 8);
                }
            }
            CP_COMMIT();

            const uint32_t stOff = (uint32_t)(kt % 3) * STAGE;
            #pragma unroll
            for (int ks = 0; ks < 4; ks++) {
                uint32_t a[4][4], bt0[4], bt1[4];
                #pragma unroll
                for (int m = 0; m < 4; m++) {
                    int phys = (aLC + 2 * ks) ^ aSw;
                    ldsm4(a[m], stOff + aRowAddr + m * 16 * ROWB + phys * 16);
                }
                {
                    int phys0 = (bLC + 2 * ks) ^ bSw;
                    int phys1 = (bLC + 2 * ks) ^ bSw2;
                    ldsm4(bt0, stOff + bRowAddr + phys0 * 16);
                    ldsm4(bt1, stOff + bRowAddr + 16 * ROWB + phys1 * 16);
                }
                uint32_t bf[4][2] = {{bt0[0], bt0[1]}, {bt0[2], bt0[3]},
                                     {bt1[0], bt1[1]}, {bt1[2], bt1[3]}};
                #pragma unroll
                for (int m = 0; m < 4; m++)
                    #pragma unroll
                    for (int f = 0; f < 4; f++)
                        mma16816(acc[m][f], a[m], bf[f]);
            }
        }

        #pragma unroll
        for (int m = 0; m < 4; m++) {
            int r0 = rowBase + wm + m * 16 + (lane >> 2);
            #pragma unroll
            for (int f = 0; f < 4; f++) {
                int c = colBase + wn + f * 8 + (lane & 3) * 2;
                float v0 = acc[m][f][0], v1 = acc[m][f][1];
                float v2 = acc[m][f][2], v3 = acc[m][f][3];
                if (MODE == MODE_QKV) {
                    float b0 = (c < 512) ? bias[c] : ((c < 1024) ? 0.f : bias2[c - 1024]);
                    float b1 = (c + 1 < 512) ? bias[c + 1] : ((c + 1 < 1024) ? 0.f : bias2[c + 1 - 1024]);
                    v0 += b0; v1 += b1; v2 += b0; v3 += b1;
                } else {
                    v0 += bias[c]; v1 += bias[c + 1]; v2 += bias[c]; v3 += bias[c + 1];
                }
                if (MODE == MODE_GELU_H) {
                    v0 = gelu_fast(v0);
                    v1 = gelu_fast(v1);
                    v2 = gelu_fast(v2);
                    v3 = gelu_fast(v3);
                }
                *(__half2*)(C + (size_t)r0 * N + c)       = __floats2half2_rn(v0, v1);
                *(__half2*)(C + (size_t)(r0 + 8) * N + c) = __floats2half2_rn(v2, v3);
            }
        }
    }
}

// ---------------- attention: register-blocked (round-14), combined table --
__global__ __launch_bounds__(256)
void attn_kernel(const float* __restrict__ logit_scale) {
    int blk  = blockIdx.x;
    int win  = blk >> 4;
    int head = blk & 15;
    __shared__ float qs[NTOKW * 32];       // [n][d], pre-scaled by rqn*scale
    __shared__ float kt[32 * NTOKW];       // [d][m], pre-scaled by rkn
    __shared__ float vs[NTOKW * 32];       // [m][d]
    __shared__ float S[NTOKW * NTOKW];
    __shared__ float rqn[NTOKW], rkn[NTOKW];
    int tid = threadIdx.x;
    int lane = tid & 31, w = tid >> 5;

    const __half* base = g_qkv16 + (size_t)win * NTOKW * 1536 + head * 32;
    if (tid < NTOKW * 4) {
        int n = tid >> 2, c8 = tid & 3;
        const __half* src = base + (size_t)n * 1536 + c8 * 8;
        uint4 uq = *(const uint4*)(src);
        uint4 uk = *(const uint4*)(src + 512);
        uint4 uv = *(const uint4*)(src + 1024);
        const __half2* hq = (const __half2*)&uq;
        const __half2* hk = (const __half2*)&uk;
        const __half2* hv = (const __half2*)&uv;
        #pragma unroll
        for (int e = 0; e < 4; e++) {
            float2 fq = __half22float2(hq[e]);
            float2 fk = __half22float2(hk[e]);
            float2 fv = __half22float2(hv[e]);
            int d = c8 * 8 + 2 * e;
            qs[n * 32 + d] = fq.x;  qs[n * 32 + d + 1] = fq.y;
            kt[d * NTOKW + n] = fk.x;  kt[(d + 1) * NTOKW + n] = fk.y;
            vs[n * 32 + d] = fv.x;  vs[n * 32 + d + 1] = fv.y;
        }
    }
    __syncthreads();

    float scale = __expf(fminf(logit_scale[head], 4.6051701859880914f));
    if (tid < 2 * NTOKW) {
        int n = tid % NTOKW;
        float s = 0.f;
        if (tid < NTOKW) {
            const float* p = qs + n * 32;
            #pragma unroll
            for (int d = 0; d < 32; d++) { float v = p[d]; s += v * v; }
            rqn[n] = rsqrtf(s) * scale;
        } else {
            #pragma unroll
            for (int d = 0; d < 32; d++) { float v = kt[d * NTOKW + n]; s += v * v; }
            rkn[n] = rsqrtf(s);
        }
    }
    __syncthreads();

    // pre-scale q rows and k columns in smem
    for (int i = tid; i < NTOKW * 32; i += 256) {
        qs[i] *= rqn[i >> 5];
        int d = i / NTOKW, m = i - d * NTOKW;
        kt[d * NTOKW + m] *= rkn[m];
    }
    __syncthreads();

    // S loop: thread (n, g) owns m = g, g+5, ... ; q row cached in registers
    const float* bm = g_bm + ((size_t)(win & 63) * 16 + head) * 2401;
    if (tid < 245) {
        int n = tid / 5, g = tid % 5;
        float qp[32];
        #pragma unroll
        for (int d = 0; d < 32; d++) qp[d] = qs[n * 32 + d];
        for (int m = g; m < NTOKW; m += 5) {
            float s = 0.f;
            #pragma unroll
            for (int d = 0; d < 32; d++) s += qp[d] * kt[d * NTOKW + m];
            int p = n * NTOKW + m;
            S[p] = s + bm[p];
        }
    }
    __syncthreads();

    // softmax (warp-parallel over rows)
    for (int r = w; r < NTOKW; r += 8) {
        float* row = S + r * NTOKW;
        float v0 = row[lane];
        float v1 = (lane < 17) ? row[32 + lane] : -1e30f;
        float mx = fmaxf(v0, v1);
        #pragma unroll
        for (int o = 16; o > 0; o >>= 1) mx = fmaxf(mx, __shfl_xor_sync(0xffffffffu, mx, o));
        float e0 = __expf(v0 - mx);
        float e1 = (lane < 17) ? __expf(v1 - mx) : 0.f;
        float s = e0 + e1;
        #pragma unroll
        for (int o = 16; o > 0; o >>= 1) s += __shfl_xor_sync(0xffffffffu, s, o);
        float inv = 1.f / s;
        row[lane] = e0 * inv;
        if (lane < 17) row[32 + lane] = e1 * inv;
    }
    __syncthreads();

    // AV: thread (n, dg) computes 8 d's; P value loaded once per m
    if (tid < 196) {
        int n = tid >> 2, dg = (tid & 3) * 8;
        const float* Pr = S + n * NTOKW;
        float acc[8];
        #pragma unroll
        for (int j = 0; j < 8; j++) acc[j] = 0.f;
        for (int m = 0; m < NTOKW; m++) {
            float p = Pr[m];
            const float* vp = vs + m * 32 + dg;
            #pragma unroll
            for (int j = 0; j < 8; j++) acc[j] += p * vp[j];
        }
        __half2* o = (__half2*)(g_attn16 + (size_t)(win * NTOKW + n) * CDIM + head * 32 + dg);
        #pragma unroll
        for (int j = 0; j < 4; j++)
            o[j] = __floats2half2_rn(acc[2 * j], acc[2 * j + 1]);
    }
}

// ---------------- LN kernels: warp per row, fp16 inputs ----------------
__global__ __launch_bounds__(256)
void post_attn_kernel(const float* __restrict__ x,
                      const float* __restrict__ g1, const float* __restrict__ b1) {
    int lane = threadIdx.x & 31;
    int p = blockIdx.x * 8 + (threadIdx.x >> 5);
    int b = p / 3136, rem = p - b * 3136;
    int h = rem / 56, w = rem - (rem / 56) * 56;
    int hs = h - 3; if (hs < 0) hs += 56;
    int ws = w - 3; if (ws < 0) ws += 56;
    int t = (b * 64 + (hs / 7) * 8 + (ws / 7)) * NTOKW + (hs % 7) * 7 + (ws % 7);

    const __half2* row = (const __half2*)(g_proj16 + (size_t)t * CDIM);
    float2 v[8];
    float s = 0.f, ss = 0.f;
    #pragma unroll
    for (int k = 0; k < 8; k++) {
        v[k] = __half22float2(row[lane + k * 32]);
        s  += v[k].x + v[k].y;
        ss += v[k].x * v[k].x + v[k].y * v[k].y;
    }
    #pragma unroll
    for (int o = 16; o > 0; o >>= 1) {
        s  += __shfl_xor_sync(0xffffffffu, s,  o);
        ss += __shfl_xor_sync(0xffffffffu, ss, o);
    }
    float mu = s * (1.f / CDIM);
    float rstd = rsqrtf(ss * (1.f / CDIM) - mu * mu + 1e-5f);
    const float2* xr = (const float2*)(x + (size_t)p * CDIM);
    float2* o1 = (float2*)(g_x1 + (size_t)p * CDIM);
    __half2* oh = (__half2*)(g_x1h + (size_t)p * CDIM);
    #pragma unroll
    for (int k = 0; k < 8; k++) {
        int c = (lane + k * 32) * 2;
        float2 xv = xr[lane + k * 32];
        float ox = xv.x + (v[k].x - mu) * rstd * g1[c + 0] + b1[c + 0];
        float oy = xv.y + (v[k].y - mu) * rstd * g1[c + 1] + b1[c + 1];
        o1[lane + k * 32] = make_float2(ox, oy);
        oh[lane + k * 32] = __floats2half2_rn(ox, oy);
    }
}

__global__ __launch_bounds__(256)
void final_kernel(const float* __restrict__ g2, const float* __restrict__ b2,
                  float* __restrict__ out) {
    int lane = threadIdx.x & 31;
    int p = blockIdx.x * 8 + (threadIdx.x >> 5);
    const __half2* row = (const __half2*)(g_h2h + (size_t)p * CDIM);
    float2 v[8];
    float s = 0.f, ss = 0.f;
    #pragma unroll
    for (int k = 0; k < 8; k++) {
        v[k] = __half22float2(row[lane + k * 32]);
        s  += v[k].x + v[k].y;
        ss += v[k].x * v[k].x + v[k].y * v[k].y;
    }
    #pragma unroll
    for (int o = 16; o > 0; o >>= 1) {
        s  += __shfl_xor_sync(0xffffffffu, s,  o);
        ss += __shfl_xor_sync(0xffffffffu, ss, o);
    }
    float mu = s * (1.f / CDIM);
    float rstd = rsqrtf(ss * (1.f / CDIM) - mu * mu + 1e-5f);
    const float2* xr = (const float2*)(g_x1 + (size_t)p * CDIM);
    float2* o1 = (float2*)(out + (size_t)p * CDIM);
    #pragma unroll
    for (int k = 0; k < 8; k++) {
        int c = (lane + k * 32) * 2;
        float2 xv = xr[lane + k * 32];
        float ox = xv.x + (v[k].x - mu) * rstd * g2[c + 0] + b2[c + 0];
        float oy = xv.y + (v[k].y - mu) * rstd * g2[c + 1] + b2[c + 1];
        o1[lane + k * 32] = make_float2(ox, oy);
    }
}

// ---------------- launch ----------------
extern "C" void kernel_launch(void* const* d_in, const int* in_sizes, int n_in,
                              void* d_out, int out_size) {
    const float* x        = (const float*)d_in[0];
    const float* qkv_w    = (const float*)d_in[1];
    const float* q_bias   = (const float*)d_in[2];
    const float* v_bias   = (const float*)d_in[3];
    const float* proj_w   = (const float*)d_in[4];
    const float* proj_b   = (const float*)d_in[5];
    const float* lscale   = (const float*)d_in[6];
    const float* cpb_w1   = (const float*)d_in[7];
    const float* cpb_b1   = (const float*)d_in[8];
    const float* cpb_w2   = (const float*)d_in[9];
    const float* rct      = (const float*)d_in[10];
    const float* gamma1   = (const float*)d_in[11];
    const float* beta1    = (const float*)d_in[12];
    const float* gamma2   = (const float*)d_in[13];
    const float* beta2    = (const float*)d_in[14];
    const float* fc1_w    = (const float*)d_in[15];
    const float* fc1_b    = (const float*)d_in[16];
    const float* fc2_w    = (const float*)d_in[17];
    const float* fc2_b    = (const float*)d_in[18];
    const int*   rpi      = (const int*)d_in[19];
    const float* amask    = (const float*)d_in[20];
    float* out = (float*)d_out;

    __half *p_xw16, *p_qkv16, *p_attn16, *p_proj16, *p_x1h, *p_hid16, *p_h2h;
    __half *wt_qkv, *wt_proj, *wt_fc1, *wt_fc2;
    cudaGetSymbolAddress((void**)&p_xw16,   g_xw16);
    cudaGetSymbolAddress((void**)&p_qkv16,  g_qkv16);
    cudaGetSymbolAddress((void**)&p_attn16, g_attn16);
    cudaGetSymbolAddress((void**)&p_proj16, g_proj16);
    cudaGetSymbolAddress((void**)&p_x1h,    g_x1h);
    cudaGetSymbolAddress((void**)&p_hid16,  g_hid16);
    cudaGetSymbolAddress((void**)&p_h2h,    g_h2h);
    cudaGetSymbolAddress((void**)&wt_qkv,   g_wt_qkv);
    cudaGetSymbolAddress((void**)&wt_proj,  g_wt_proj);
    cudaGetSymbolAddress((void**)&wt_fc1,   g_wt_fc1);
    cudaGetSymbolAddress((void**)&wt_fc2,   g_wt_fc2);

    cudaFuncSetAttribute((const void*)hgemm_kernel<MODE_QKV, 0>,
                         cudaFuncAttributeMaxDynamicSharedMemorySize, HG_SMEM);
    cudaFuncSetAttribute((const void*)hgemm_kernel<MODE_BIAS, 0>,
                         cudaFuncAttributeMaxDynamicSharedMemorySize, HG_SMEM);
    cudaFuncSetAttribute((const void*)hgemm_kernel<MODE_GELU_H, 0>,
                         cudaFuncAttributeMaxDynamicSharedMemorySize, HG_SMEM);
    cudaFuncSetAttribute((const void*)hgemm_kernel<MODE_BIAS, 1>,
                         cudaFuncAttributeMaxDynamicSharedMemorySize, HG_SMEM);

    int dev = 0, nsm = 148;
    cudaGetDevice(&dev);
    cudaDeviceGetAttribute(&nsm, cudaDevAttrMultiProcessorCount, dev);
    const int PGRID = nsm * 2;   // persistent grid, 2 CTAs/SM

    // 0. fused prep
    prep_kernel<<<3072 + TOK / 2, 256>>>(x, qkv_w, proj_w, fc1_w, fc2_w);

    // 1. continuous position bias -> combined bias+mask table
    cpb_table_kernel<<<169, 512>>>(rct, cpb_w1, cpb_b1, cpb_w2);
    bm_kernel<<<(64 * 16 * 2401 + 255) / 256, 256>>>(rpi, amask);

    // 2. QKV GEMM
    hgemm_kernel<MODE_QKV, 0><<<PGRID, 256, HG_SMEM>>>(
        p_xw16, wt_qkv, p_qkv16, TOK, 1536, 512, q_bias, v_bias);

    // 3. windowed cosine attention
    attn_kernel<<<NWIN * NHEAD, 256>>>(lscale);

    // 4. output projection
    hgemm_kernel<MODE_BIAS, 0><<<PGRID, 256, HG_SMEM>>>(
        p_attn16, wt_proj, p_proj16, TOK, CDIM, CDIM, proj_b, nullptr);

    // 5. window reverse + un-roll + LN + residual
    post_attn_kernel<<<TOK / 8, 256>>>(x, gamma1, beta1);

    // 6. MLP (fc2 tx-fastest: A exceeds L2)
    hgemm_kernel<MODE_GELU_H, 0><<<PGRID, 256, HG_SMEM>>>(
        p_x1h, wt_fc1, p_hid16, TOK, HID, 512, fc1_b, nullptr);
    hgemm_kernel<MODE_BIAS, 1><<<PGRID, 256, HG_SMEM>>>(
        p_hid16, wt_fc2, p_h2h, TOK, CDIM, HID, fc2_b, nullptr);

    // 7. final LN + residual
    final_kernel<<<TOK / 8, 256>>>(gamma2, beta2, out);
}